// round 10
// baseline (speedup 1.0000x reference)
#include <cuda_runtime.h>
#include <cuda_fp16.h>
#include <cstdint>

// Problem constants: x (32, 64, 64, 64) fp32, codebook (1024, 64) fp32
#define DD     64
#define KK     1024
#define BB     32
#define HWN    4096
#define NPTS   (BB * HWN)

#define MT     128          // points per CTA
#define NC     64           // codes per chunk
#define NCHUNK (KK / NC)    // 16
#define NTHR   128          // 4 warps
#define MARGIN 2e-3f        // 40x the hi/lo-split score error bound (~5e-5)

typedef unsigned long long ull;

// Codebook pre-packed as mma.sync B fragments (fp16 hi/lo split),
// exact ||c||^2 (reference-matching accumulation order), and -0.5||c||^2.
__device__ ull   g_bh[(KK / 8) * 4 * 32];
__device__ ull   g_bl[(KK / 8) * 4 * 32];
__device__ float g_norm[KK];    // EXACT: float4 / 4-acc / (s0+s1)+(s2+s3)
__device__ float g_mh[KK];      // -0.5 * g_norm (approximate filter only)

__device__ __forceinline__ void split16(float v, uint16_t &h, uint16_t &l) {
    __half hh = __float2half_rn(v);
    __half ll = __float2half_rn(v - __half2float(hh));
    h = __half_as_ushort(hh);
    l = __half_as_ushort(ll);
}
__device__ __forceinline__ uint32_t pk(uint16_t a, uint16_t b) {
    return (uint32_t)a | ((uint32_t)b << 16);
}

__device__ __forceinline__ void mma16816(float acc[4], uint4 a, ull b) {
    uint32_t b0 = (uint32_t)b, b1 = (uint32_t)(b >> 32);
    asm volatile(
        "mma.sync.aligned.m16n8k16.row.col.f32.f16.f16.f32 "
        "{%0,%1,%2,%3},{%4,%5,%6,%7},{%8,%9},{%0,%1,%2,%3};"
        : "+f"(acc[0]), "+f"(acc[1]), "+f"(acc[2]), "+f"(acc[3])
        : "r"(a.x), "r"(a.y), "r"(a.z), "r"(a.w), "r"(b0), "r"(b1));
}

// ---- prep: pack codebook fragments (hi/lo) + exact ||c||^2 ----
__global__ void cbprep_kernel(const float* __restrict__ cb) {
    int t = blockIdx.x * blockDim.x + threadIdx.x;   // 0..16383
    int lane = t & 31, ks = (t >> 5) & 3, nt = t >> 7;
    int g = lane >> 2, tg = lane & 3;
    int n = nt * 8 + g;
    int k0 = ks * 16 + 2 * tg;
    const float* row = cb + (size_t)n * DD;
    float v0 = row[k0], v1 = row[k0 + 1], v2 = row[k0 + 8], v3 = row[k0 + 9];
    uint16_t h0, l0, h1, l1, h2, l2, h3, l3;
    split16(v0, h0, l0); split16(v1, h1, l1);
    split16(v2, h2, l2); split16(v3, h3, l3);
    g_bh[t] = (ull)pk(h0, h1) | ((ull)pk(h2, h3) << 32);
    g_bl[t] = (ull)pk(l0, l1) | ((ull)pk(l2, l3) << 32);

    if (t < KK) {
        const float4* r4 = (const float4*)(cb + (size_t)t * DD);
        float s0 = 0.f, s1 = 0.f, s2 = 0.f, s3 = 0.f;
        #pragma unroll
        for (int q = 0; q < DD / 4; q++) {
            float4 c = r4[q];
            s0 = fmaf(c.x, c.x, s0);
            s1 = fmaf(c.y, c.y, s1);
            s2 = fmaf(c.z, c.z, s2);
            s3 = fmaf(c.w, c.w, s3);
        }
        float norm = (s0 + s1) + (s2 + s3);
        g_norm[t] = norm;
        g_mh[t]   = -0.5f * norm;
    }
}

// ---- shared layout (B staging removed) ----
#define OFF_AH   0            // 1024 x uint4  16 KB; reused as rescue scratch
#define OFF_AL   16384        // 16 KB
#define OFF_MH   32768        // float[1024]    4 KB
#define OFF_SIDX 36864        // int[128]
#define OFF_FLG  37376        // int[128]
#define OFF_NFLG 37888        // int
#define SMEM_TOTAL 38016

__global__ void __launch_bounds__(NTHR, 4) vq_kernel(
    const float* __restrict__ x,
    const float* __restrict__ cb,
    float* __restrict__ out,
    int write_idx
) {
    extern __shared__ char smem[];
    uint4* sah = (uint4*)(smem + OFF_AH);
    uint4* sal = (uint4*)(smem + OFF_AL);
    float* smh = (float*)(smem + OFF_MH);
    int*   sidx = (int*)(smem + OFF_SIDX);
    int*   sflg = (int*)(smem + OFF_FLG);
    int*   nflg = (int*)(smem + OFF_NFLG);

    const int tid = threadIdx.x;
    const int w = tid >> 5, lane = tid & 31;
    const int g = lane >> 2, tg = lane & 3;

    const int p0 = blockIdx.x * MT;
    const int b  = p0 >> 12;
    const int n0 = p0 & (HWN - 1);
    const float* xb = x + (size_t)b * DD * HWN + n0;

    if (tid == 0) *nflg = 0;
    for (int i = tid; i < KK; i += NTHR) smh[i] = g_mh[i];

    // ---- stage A: x[b, k, n0+m] -> fp16 hi/lo fragment layout (one-time) ----
    #pragma unroll
    for (int i = 0; i < 8; i++) {
        int f  = tid + i * NTHR;
        int fl = f & 31, ks = (f >> 5) & 3, mt = f >> 7;
        int fg = fl >> 2, ftg = fl & 3;
        int m  = mt * 16 + fg;
        int k0 = ks * 16 + 2 * ftg;
        const float* p = xb + m;
        const float* q = p + 8;
        float v00 = p[(size_t)k0 * HWN],       v01 = p[(size_t)(k0 + 1) * HWN];
        float v02 = p[(size_t)(k0 + 8) * HWN], v03 = p[(size_t)(k0 + 9) * HWN];
        float v10 = q[(size_t)k0 * HWN],       v11 = q[(size_t)(k0 + 1) * HWN];
        float v12 = q[(size_t)(k0 + 8) * HWN], v13 = q[(size_t)(k0 + 9) * HWN];
        uint16_t h[8], l[8];
        split16(v00, h[0], l[0]); split16(v01, h[1], l[1]);
        split16(v02, h[2], l[2]); split16(v03, h[3], l[3]);
        split16(v10, h[4], l[4]); split16(v11, h[5], l[5]);
        split16(v12, h[6], l[6]); split16(v13, h[7], l[7]);
        uint4 H = make_uint4(pk(h[0], h[1]), pk(h[4], h[5]), pk(h[2], h[3]), pk(h[6], h[7]));
        uint4 L = make_uint4(pk(l[0], l[1]), pk(l[4], l[5]), pk(l[2], l[3]), pk(l[6], l[7]));
        int idx = (mt * 4 + ks) * 32 + fl;
        sah[idx] = H;
        sal[idx] = L;
    }
    __syncthreads();   // the ONLY barrier before the epilogue phase

    float best[4], sec[4];
    int   bidx[4];
    #pragma unroll
    for (int i = 0; i < 4; i++) { best[i] = -3.4e38f; sec[i] = -3.4e38f; bidx[i] = 0; }

    const int mt0 = w * 2, mt1 = w * 2 + 1;

    for (int ch = 0; ch < NCHUNK; ch++) {
        // B fragments loaded straight from global (L1/L2-hot, same across warps/CTAs)
        const ull* bhp = g_bh + (size_t)ch * 1024 + lane;
        const ull* blp = g_bl + (size_t)ch * 1024 + lane;

        float acc[2][8][4];
        #pragma unroll
        for (int mt = 0; mt < 2; mt++)
            #pragma unroll
            for (int j = 0; j < 8; j++)
                #pragma unroll
                for (int c = 0; c < 4; c++) acc[mt][j][c] = 0.f;

        #pragma unroll
        for (int ks = 0; ks < 4; ks++) {
            uint4 ah0 = sah[(mt0 * 4 + ks) * 32 + lane];
            uint4 al0 = sal[(mt0 * 4 + ks) * 32 + lane];
            uint4 ah1 = sah[(mt1 * 4 + ks) * 32 + lane];
            uint4 al1 = sal[(mt1 * 4 + ks) * 32 + lane];
            #pragma unroll
            for (int j = 0; j < 8; j++) {
                ull bh = __ldg(bhp + (j * 4 + ks) * 32);
                ull bl = __ldg(blp + (j * 4 + ks) * 32);
                mma16816(acc[0][j], ah0, bh);
                mma16816(acc[0][j], ah0, bl);
                mma16816(acc[0][j], al0, bh);
                mma16816(acc[1][j], ah1, bh);
                mma16816(acc[1][j], ah1, bl);
                mma16816(acc[1][j], al1, bh);
            }
        }

        // epilogue: track approx top-2 per point (ascending k)
        #pragma unroll
        for (int j = 0; j < 8; j++) {
            int kb = ch * NC + j * 8 + 2 * tg;
            float mh0 = smh[kb], mh1 = smh[kb + 1];
            #pragma unroll
            for (int mt = 0; mt < 2; mt++) {
                float s0 = acc[mt][j][0] + mh0;
                float s1 = acc[mt][j][1] + mh1;
                float s2 = acc[mt][j][2] + mh0;
                float s3 = acc[mt][j][3] + mh1;
                int ia = mt * 2, ib2 = mt * 2 + 1;
                if (s0 > best[ia]) { sec[ia] = best[ia]; best[ia] = s0; bidx[ia] = kb; }
                else if (s0 > sec[ia]) sec[ia] = s0;
                if (s1 > best[ia]) { sec[ia] = best[ia]; best[ia] = s1; bidx[ia] = kb + 1; }
                else if (s1 > sec[ia]) sec[ia] = s1;
                if (s2 > best[ib2]) { sec[ib2] = best[ib2]; best[ib2] = s2; bidx[ib2] = kb; }
                else if (s2 > sec[ib2]) sec[ib2] = s2;
                if (s3 > best[ib2]) { sec[ib2] = best[ib2]; best[ib2] = s3; bidx[ib2] = kb + 1; }
                else if (s3 > sec[ib2]) sec[ib2] = s3;
            }
        }
    }

    // cross-lane top-2 merge (4 lanes per point), index tie-break
    #pragma unroll
    for (int i = 0; i < 4; i++) {
        #pragma unroll
        for (int m = 1; m <= 2; m <<= 1) {
            float ob = __shfl_xor_sync(0xffffffffu, best[i], m);
            float os = __shfl_xor_sync(0xffffffffu, sec[i], m);
            int   oi = __shfl_xor_sync(0xffffffffu, bidx[i], m);
            if (ob > best[i] || (ob == best[i] && oi < bidx[i])) {
                float t = best[i];
                best[i] = ob; bidx[i] = oi;
                sec[i] = (os > t) ? os : t;
            } else {
                sec[i] = (ob > sec[i]) ? ob : sec[i];
            }
        }
    }
    if (tg == 0) {
        #pragma unroll
        for (int i = 0; i < 4; i++) {
            int pl = w * 32 + (i >> 1) * 16 + (i & 1) * 8 + g;
            sidx[pl] = bidx[i];
            if (best[i] - sec[i] < MARGIN) {
                int slot = atomicAdd(nflg, 1);
                if (slot < MT) sflg[slot] = pl;
            }
        }
    }
    __syncthreads();

    // ---- exact fp32 rescue (verified: bit-matches the reference):
    //      dot: float4 / 4-acc / (d0+d1)+(d2+d3); score = fmaf(-2, dot, g_norm[k]);
    //      strict < argmin ascending k; cross-lane index tie-break. ----
    {
        int nfr = *nflg;
        int overflow = (nfr > MT);
        int nf = overflow ? MT : nfr;
        float* xs = (float*)(smem + OFF_AH) + w * 64;   // sah dead now
        for (int f = w; f < nf; f += 4) {
            int pl = overflow ? f : sflg[f];
            xs[lane]      = xb[(size_t)lane * HWN + pl];
            xs[lane + 32] = xb[(size_t)(lane + 32) * HWN + pl];
            __syncwarp();
            float bb = 3.4e38f;
            int   bi = 0;
            for (int j = 0; j < 32; j++) {
                int k = j * 32 + lane;
                const float4* crow = (const float4*)(cb + (size_t)k * DD);
                float d0 = 0.f, d1 = 0.f, d2 = 0.f, d3 = 0.f;
                #pragma unroll
                for (int q = 0; q < 16; q++) {
                    float4 c = __ldg(crow + q);
                    d0 = fmaf(xs[4 * q + 0], c.x, d0);
                    d1 = fmaf(xs[4 * q + 1], c.y, d1);
                    d2 = fmaf(xs[4 * q + 2], c.z, d2);
                    d3 = fmaf(xs[4 * q + 3], c.w, d3);
                }
                float dot = (d0 + d1) + (d2 + d3);
                float s   = fmaf(-2.0f, dot, __ldg(&g_norm[k]));
                if (s < bb) { bb = s; bi = k; }
            }
            #pragma unroll
            for (int m = 16; m >= 1; m >>= 1) {
                float ob = __shfl_xor_sync(0xffffffffu, bb, m);
                int   oi = __shfl_xor_sync(0xffffffffu, bi, m);
                if (ob < bb || (ob == bb && oi < bi)) { bb = ob; bi = oi; }
            }
            if (lane == 0) sidx[pl] = bi;
            __syncwarp();
        }
    }
    __syncthreads();

    // exact fp32 gather, coalesced over points
    float* ob = out + (size_t)b * DD * HWN + n0;
    #pragma unroll
    for (int i = tid; i < MT * DD; i += NTHR) {
        int pl = i & (MT - 1);
        int d  = i >> 7;
        ob[(size_t)d * HWN + pl] = __ldg(&cb[(size_t)sidx[pl] * DD + d]);
    }
    if (write_idx)
        out[(size_t)BB * DD * HWN + p0 + tid] = (float)sidx[tid];
}

extern "C" void kernel_launch(void* const* d_in, const int* in_sizes, int n_in,
                              void* d_out, int out_size) {
    const float* x  = (const float*)d_in[0];
    const float* cb = (const float*)d_in[1];
    float* out = (float*)d_out;

    static int inited = 0;
    if (!inited) {
        cudaFuncSetAttribute(vq_kernel, cudaFuncAttributeMaxDynamicSharedMemorySize, SMEM_TOTAL);
        inited = 1;
    }

    cbprep_kernel<<<64, 256>>>(cb);

    int write_idx = (out_size >= BB * DD * HWN + NPTS) ? 1 : 0;
    vq_kernel<<<NPTS / MT, NTHR, SMEM_TOTAL>>>(x, cb, out, write_idx);
}

// round 11
// speedup vs baseline: 1.2455x; 1.2455x over previous
#include <cuda_runtime.h>
#include <cuda_fp16.h>
#include <cstdint>

// Problem constants: x (32, 64, 64, 64) fp32, codebook (1024, 64) fp32
#define DD     64
#define KK     1024
#define BB     32
#define HWN    4096
#define NPTS   (BB * HWN)

#define MT     128          // points per CTA
#define NC     64           // codes per chunk
#define NCHUNK (KK / NC)    // 16
#define NTHR   128          // 4 warps
#define MARGIN 2e-3f        // 40x the hi/lo-split score error bound (~5e-5)

typedef unsigned long long ull;

// Codebook pre-packed as mma.sync B fragments (fp16 hi/lo split),
// exact ||c||^2 (reference-matching accumulation order), and -0.5||c||^2.
__device__ ull   g_bh[(KK / 8) * 4 * 32];
__device__ ull   g_bl[(KK / 8) * 4 * 32];
__device__ float g_norm[KK];    // EXACT: float4 / 4-acc / (s0+s1)+(s2+s3)
__device__ float g_mh[KK];      // -0.5 * g_norm (approximate filter only)

__device__ __forceinline__ void split16(float v, uint16_t &h, uint16_t &l) {
    __half hh = __float2half_rn(v);
    __half ll = __float2half_rn(v - __half2float(hh));
    h = __half_as_ushort(hh);
    l = __half_as_ushort(ll);
}
__device__ __forceinline__ uint32_t pk(uint16_t a, uint16_t b) {
    return (uint32_t)a | ((uint32_t)b << 16);
}

__device__ __forceinline__ void mma16816(float acc[4], uint4 a, ull b) {
    uint32_t b0 = (uint32_t)b, b1 = (uint32_t)(b >> 32);
    asm volatile(
        "mma.sync.aligned.m16n8k16.row.col.f32.f16.f16.f32 "
        "{%0,%1,%2,%3},{%4,%5,%6,%7},{%8,%9},{%0,%1,%2,%3};"
        : "+f"(acc[0]), "+f"(acc[1]), "+f"(acc[2]), "+f"(acc[3])
        : "r"(a.x), "r"(a.y), "r"(a.z), "r"(a.w), "r"(b0), "r"(b1));
}

// ---- prep: pack codebook fragments (hi/lo) + exact ||c||^2 ----
__global__ void cbprep_kernel(const float* __restrict__ cb) {
    int t = blockIdx.x * blockDim.x + threadIdx.x;   // 0..16383
    int lane = t & 31, ks = (t >> 5) & 3, nt = t >> 7;
    int g = lane >> 2, tg = lane & 3;
    int n = nt * 8 + g;
    int k0 = ks * 16 + 2 * tg;
    const float* row = cb + (size_t)n * DD;
    float v0 = row[k0], v1 = row[k0 + 1], v2 = row[k0 + 8], v3 = row[k0 + 9];
    uint16_t h0, l0, h1, l1, h2, l2, h3, l3;
    split16(v0, h0, l0); split16(v1, h1, l1);
    split16(v2, h2, l2); split16(v3, h3, l3);
    g_bh[t] = (ull)pk(h0, h1) | ((ull)pk(h2, h3) << 32);
    g_bl[t] = (ull)pk(l0, l1) | ((ull)pk(l2, l3) << 32);

    if (t < KK) {
        const float4* r4 = (const float4*)(cb + (size_t)t * DD);
        float s0 = 0.f, s1 = 0.f, s2 = 0.f, s3 = 0.f;
        #pragma unroll
        for (int q = 0; q < DD / 4; q++) {
            float4 c = r4[q];
            s0 = fmaf(c.x, c.x, s0);
            s1 = fmaf(c.y, c.y, s1);
            s2 = fmaf(c.z, c.z, s2);
            s3 = fmaf(c.w, c.w, s3);
        }
        float norm = (s0 + s1) + (s2 + s3);
        g_norm[t] = norm;
        g_mh[t]   = -0.5f * norm;
    }
}

// ---- shared layout (B staging removed) ----
#define OFF_AH   0            // 1024 x uint4  16 KB; reused as rescue scratch
#define OFF_AL   16384        // 16 KB
#define OFF_MH   32768        // float[1024]    4 KB
#define OFF_SIDX 36864        // int[128]
#define OFF_FLG  37376        // int[128]
#define OFF_NFLG 37888        // int
#define SMEM_TOTAL 38016

// Branch-free top-2 update: 6 issue slots, no BSSY/BSYNC.
// Strict > keeps the FIRST (lowest-k) max; duplicate max -> sec==best -> flagged.
#define UPD(s, kk, ii)                                   \
    {                                                    \
        float _mn = fminf((s), best[ii]);                \
        bidx[ii] = ((s) > best[ii]) ? (kk) : bidx[ii];   \
        best[ii] = fmaxf((s), best[ii]);                 \
        sec[ii]  = fmaxf(sec[ii], _mn);                  \
    }

__global__ void __launch_bounds__(NTHR, 4) vq_kernel(
    const float* __restrict__ x,
    const float* __restrict__ cb,
    float* __restrict__ out,
    int write_idx
) {
    extern __shared__ char smem[];
    uint4* sah = (uint4*)(smem + OFF_AH);
    uint4* sal = (uint4*)(smem + OFF_AL);
    float* smh = (float*)(smem + OFF_MH);
    int*   sidx = (int*)(smem + OFF_SIDX);
    int*   sflg = (int*)(smem + OFF_FLG);
    int*   nflg = (int*)(smem + OFF_NFLG);

    const int tid = threadIdx.x;
    const int w = tid >> 5, lane = tid & 31;
    const int g = lane >> 2, tg = lane & 3;

    const int p0 = blockIdx.x * MT;
    const int b  = p0 >> 12;
    const int n0 = p0 & (HWN - 1);
    const float* xb = x + (size_t)b * DD * HWN + n0;

    if (tid == 0) *nflg = 0;
    for (int i = tid; i < KK; i += NTHR) smh[i] = g_mh[i];

    // ---- stage A: x[b, k, n0+m] -> fp16 hi/lo fragment layout (one-time) ----
    #pragma unroll
    for (int i = 0; i < 8; i++) {
        int f  = tid + i * NTHR;
        int fl = f & 31, ks = (f >> 5) & 3, mt = f >> 7;
        int fg = fl >> 2, ftg = fl & 3;
        int m  = mt * 16 + fg;
        int k0 = ks * 16 + 2 * ftg;
        const float* p = xb + m;
        const float* q = p + 8;
        float v00 = p[(size_t)k0 * HWN],       v01 = p[(size_t)(k0 + 1) * HWN];
        float v02 = p[(size_t)(k0 + 8) * HWN], v03 = p[(size_t)(k0 + 9) * HWN];
        float v10 = q[(size_t)k0 * HWN],       v11 = q[(size_t)(k0 + 1) * HWN];
        float v12 = q[(size_t)(k0 + 8) * HWN], v13 = q[(size_t)(k0 + 9) * HWN];
        uint16_t h[8], l[8];
        split16(v00, h[0], l[0]); split16(v01, h[1], l[1]);
        split16(v02, h[2], l[2]); split16(v03, h[3], l[3]);
        split16(v10, h[4], l[4]); split16(v11, h[5], l[5]);
        split16(v12, h[6], l[6]); split16(v13, h[7], l[7]);
        uint4 H = make_uint4(pk(h[0], h[1]), pk(h[4], h[5]), pk(h[2], h[3]), pk(h[6], h[7]));
        uint4 L = make_uint4(pk(l[0], l[1]), pk(l[4], l[5]), pk(l[2], l[3]), pk(l[6], l[7]));
        int idx = (mt * 4 + ks) * 32 + fl;
        sah[idx] = H;
        sal[idx] = L;
    }
    __syncthreads();

    float best[4], sec[4];
    int   bidx[4];
    #pragma unroll
    for (int i = 0; i < 4; i++) { best[i] = -3.4e38f; sec[i] = -3.4e38f; bidx[i] = 0; }

    const int mt0 = w * 2, mt1 = w * 2 + 1;

    for (int ch = 0; ch < NCHUNK; ch++) {
        const ull* bhp = g_bh + (size_t)ch * 1024 + lane;
        const ull* blp = g_bl + (size_t)ch * 1024 + lane;

        float acc[2][8][4];
        #pragma unroll
        for (int mt = 0; mt < 2; mt++)
            #pragma unroll
            for (int j = 0; j < 8; j++)
                #pragma unroll
                for (int c = 0; c < 4; c++) acc[mt][j][c] = 0.f;

        #pragma unroll
        for (int ks = 0; ks < 4; ks++) {
            uint4 ah0 = sah[(mt0 * 4 + ks) * 32 + lane];
            uint4 al0 = sal[(mt0 * 4 + ks) * 32 + lane];
            uint4 ah1 = sah[(mt1 * 4 + ks) * 32 + lane];
            uint4 al1 = sal[(mt1 * 4 + ks) * 32 + lane];
            #pragma unroll
            for (int j = 0; j < 8; j++) {
                ull bh = __ldg(bhp + (j * 4 + ks) * 32);
                ull bl = __ldg(blp + (j * 4 + ks) * 32);
                mma16816(acc[0][j], ah0, bh);
                mma16816(acc[0][j], ah0, bl);
                mma16816(acc[0][j], al0, bh);
                mma16816(acc[1][j], ah1, bh);
                mma16816(acc[1][j], ah1, bl);
                mma16816(acc[1][j], al1, bh);
            }
        }

        // branch-free top-2 epilogue (ascending k)
        #pragma unroll
        for (int j = 0; j < 8; j++) {
            int kb = ch * NC + j * 8 + 2 * tg;
            float2 mhv = *(const float2*)&smh[kb];
            #pragma unroll
            for (int mt = 0; mt < 2; mt++) {
                int ia = mt * 2, ib2 = mt * 2 + 1;
                float s0 = acc[mt][j][0] + mhv.x;
                float s1 = acc[mt][j][1] + mhv.y;
                float s2 = acc[mt][j][2] + mhv.x;
                float s3 = acc[mt][j][3] + mhv.y;
                UPD(s0, kb,     ia);
                UPD(s1, kb + 1, ia);
                UPD(s2, kb,     ib2);
                UPD(s3, kb + 1, ib2);
            }
        }
    }

    // cross-lane top-2 merge (4 lanes per point), index tie-break
    #pragma unroll
    for (int i = 0; i < 4; i++) {
        #pragma unroll
        for (int m = 1; m <= 2; m <<= 1) {
            float ob = __shfl_xor_sync(0xffffffffu, best[i], m);
            float os = __shfl_xor_sync(0xffffffffu, sec[i], m);
            int   oi = __shfl_xor_sync(0xffffffffu, bidx[i], m);
            if (ob > best[i] || (ob == best[i] && oi < bidx[i])) {
                float t = best[i];
                best[i] = ob; bidx[i] = oi;
                sec[i] = (os > t) ? os : t;
            } else {
                sec[i] = (ob > sec[i]) ? ob : sec[i];
            }
        }
    }
    if (tg == 0) {
        #pragma unroll
        for (int i = 0; i < 4; i++) {
            int pl = w * 32 + (i >> 1) * 16 + (i & 1) * 8 + g;
            sidx[pl] = bidx[i];
            if (best[i] - sec[i] < MARGIN) {
                int slot = atomicAdd(nflg, 1);
                if (slot < MT) sflg[slot] = pl;
            }
        }
    }
    __syncthreads();

    // ---- exact fp32 rescue (verified: bit-matches the reference) ----
    {
        int nfr = *nflg;
        int overflow = (nfr > MT);
        int nf = overflow ? MT : nfr;
        float* xs = (float*)(smem + OFF_AH) + w * 64;   // sah dead now
        for (int f = w; f < nf; f += 4) {
            int pl = overflow ? f : sflg[f];
            xs[lane]      = xb[(size_t)lane * HWN + pl];
            xs[lane + 32] = xb[(size_t)(lane + 32) * HWN + pl];
            __syncwarp();
            float bb = 3.4e38f;
            int   bi = 0;
            for (int j = 0; j < 32; j++) {
                int k = j * 32 + lane;
                const float4* crow = (const float4*)(cb + (size_t)k * DD);
                float d0 = 0.f, d1 = 0.f, d2 = 0.f, d3 = 0.f;
                #pragma unroll
                for (int q = 0; q < 16; q++) {
                    float4 c = __ldg(crow + q);
                    d0 = fmaf(xs[4 * q + 0], c.x, d0);
                    d1 = fmaf(xs[4 * q + 1], c.y, d1);
                    d2 = fmaf(xs[4 * q + 2], c.z, d2);
                    d3 = fmaf(xs[4 * q + 3], c.w, d3);
                }
                float dot = (d0 + d1) + (d2 + d3);
                float s   = fmaf(-2.0f, dot, __ldg(&g_norm[k]));
                if (s < bb) { bb = s; bi = k; }
            }
            #pragma unroll
            for (int m = 16; m >= 1; m >>= 1) {
                float ob = __shfl_xor_sync(0xffffffffu, bb, m);
                int   oi = __shfl_xor_sync(0xffffffffu, bi, m);
                if (ob < bb || (ob == bb && oi < bi)) { bb = ob; bi = oi; }
            }
            if (lane == 0) sidx[pl] = bi;
            __syncwarp();
        }
    }
    __syncthreads();

    // exact fp32 gather, coalesced over points
    float* ob = out + (size_t)b * DD * HWN + n0;
    #pragma unroll
    for (int i = tid; i < MT * DD; i += NTHR) {
        int pl = i & (MT - 1);
        int d  = i >> 7;
        ob[(size_t)d * HWN + pl] = __ldg(&cb[(size_t)sidx[pl] * DD + d]);
    }
    if (write_idx)
        out[(size_t)BB * DD * HWN + p0 + tid] = (float)sidx[tid];
}

extern "C" void kernel_launch(void* const* d_in, const int* in_sizes, int n_in,
                              void* d_out, int out_size) {
    const float* x  = (const float*)d_in[0];
    const float* cb = (const float*)d_in[1];
    float* out = (float*)d_out;

    static int inited = 0;
    if (!inited) {
        cudaFuncSetAttribute(vq_kernel, cudaFuncAttributeMaxDynamicSharedMemorySize, SMEM_TOTAL);
        inited = 1;
    }

    cbprep_kernel<<<64, 256>>>(cb);

    int write_idx = (out_size >= BB * DD * HWN + NPTS) ? 1 : 0;
    vq_kernel<<<NPTS / MT, NTHR, SMEM_TOTAL>>>(x, cb, out, write_idx);
}